// round 1
// baseline (speedup 1.0000x reference)
#include <cuda_runtime.h>
#include <cuda_bf16.h>

// ---------------------------------------------------------------------------
// Self-attention block, fp32 baseline.
//   B=4, Cin=512, Ck=Cv=256, Cout=512, H=W=64, N=4096
// Pipeline:
//   h  = relu(bn(W1 x))          (k and q branches, per batch GEMM 256x4096x512)
//   K  = relu(bn(W2 h))          (256x4096x256)
//   Q  = relu(bn(W2 h))
//   V  = Wv x + bv               (256x4096x512)
//   S  = (Q^T K) / 16            (4096x4096x256)
//   P  = softmax_rows(S)
//   ctx= V P^T                   (256x4096x4096)
//   out= Wo ctx + bo             (512x4096x256)
// ---------------------------------------------------------------------------

#define EPSV 1e-5f

// Scratch (static __device__ arrays: allowed; no allocations in kernel_launch)
__device__ float g_h  [4LL * 256 * 4096];   // branch intermediate (reused k then q)
__device__ float g_K  [4LL * 256 * 4096];
__device__ float g_Q  [4LL * 256 * 4096];
__device__ float g_V  [4LL * 256 * 4096];
__device__ float g_ctx[4LL * 256 * 4096];
__device__ float g_S  [4LL * 4096 * 4096];  // 268 MB attention logits / probs

// ---------------------------------------------------------------------------
// Generic tiled SGEMM: C[m,n] = epi( sum_k A[m,k]*B[k,n] )
//   TA: 0 -> A stored row-major M x K (K contiguous)
//       1 -> A stored K x M (M contiguous), i.e. logical A[m,k] = Astore[k*M+m]
//   TB: 0 -> B stored row-major K x N (N contiguous)
//       1 -> B stored N x K (K contiguous), i.e. logical B[k,n] = Bstore[n*K+k]
//   EPI: 0 -> + bias[m]
//        1 -> relu((acc + bias[m])*s[m] + t[m]),  s=g*rsqrt(v+eps), t=beta-m*s
//        2 -> acc * scale
// Tile: 128x128, BK=8, 256 threads, 8x8 per thread (4+4 split register tiling).
// All dims assumed divisible: M%128==0, N%128==0, K%8==0 (true for all calls).
// ---------------------------------------------------------------------------
template <int TA, int TB, int EPI>
__global__ void __launch_bounds__(256)
gemm_kernel(const float* __restrict__ A, long long sAb,
            const float* __restrict__ B, long long sBb,
            float* __restrict__ C, long long sCb,
            int M, int N, int K,
            const float* __restrict__ bias,
            const float* __restrict__ gam, const float* __restrict__ bet,
            const float* __restrict__ mu,  const float* __restrict__ var,
            float scale)
{
    const int BM = 128, BN = 128, BK = 8;
    __shared__ float As[BK][BM];
    __shared__ float Bs[BK][BN];

    const int b = blockIdx.z;
    A += (long long)b * sAb;
    B += (long long)b * sBb;
    C += (long long)b * sCb;

    const int m0 = blockIdx.y * BM;
    const int n0 = blockIdx.x * BN;
    const int tid = threadIdx.x;
    const int tx = tid & 15;        // 16 cols of threads
    const int ty = tid >> 4;        // 16 rows of threads

    float acc[8][8];
#pragma unroll
    for (int i = 0; i < 8; i++)
#pragma unroll
        for (int j = 0; j < 8; j++) acc[i][j] = 0.f;

    for (int k0 = 0; k0 < K; k0 += BK) {
        // ---- load A tile into As[k][m] ----
        if (TA == 0) {
            // A[m,k], K contiguous: 128 rows x 8 k; 2 float4 per row
            const int r = tid >> 1, cg = (tid & 1) * 4;
            float4 v = *(const float4*)&A[(long long)(m0 + r) * K + k0 + cg];
            As[cg + 0][r] = v.x; As[cg + 1][r] = v.y;
            As[cg + 2][r] = v.z; As[cg + 3][r] = v.w;
        } else {
            // Astore[k][m], M contiguous: 8 rows x 128 m
            const int r = tid >> 5, c4 = (tid & 31) * 4;
            float4 v = *(const float4*)&A[(long long)(k0 + r) * M + m0 + c4];
            *(float4*)&As[r][c4] = v;
        }
        // ---- load B tile into Bs[k][n] ----
        if (TB == 0) {
            const int r = tid >> 5, c4 = (tid & 31) * 4;
            float4 v = *(const float4*)&B[(long long)(k0 + r) * N + n0 + c4];
            *(float4*)&Bs[r][c4] = v;
        } else {
            // Bstore[n][k], K contiguous: 128 n-rows x 8 k; 2 float4 per row
            const int r = tid >> 1, cg = (tid & 1) * 4;
            float4 v = *(const float4*)&B[(long long)(n0 + r) * K + k0 + cg];
            Bs[cg + 0][r] = v.x; Bs[cg + 1][r] = v.y;
            Bs[cg + 2][r] = v.z; Bs[cg + 3][r] = v.w;
        }
        __syncthreads();

#pragma unroll
        for (int k = 0; k < BK; k++) {
            float4 a0 = *(const float4*)&As[k][ty * 4];
            float4 a1 = *(const float4*)&As[k][64 + ty * 4];
            float4 b0 = *(const float4*)&Bs[k][tx * 4];
            float4 b1 = *(const float4*)&Bs[k][64 + tx * 4];
            float af[8] = {a0.x, a0.y, a0.z, a0.w, a1.x, a1.y, a1.z, a1.w};
            float bf[8] = {b0.x, b0.y, b0.z, b0.w, b1.x, b1.y, b1.z, b1.w};
#pragma unroll
            for (int i = 0; i < 8; i++)
#pragma unroll
                for (int j = 0; j < 8; j++)
                    acc[i][j] += af[i] * bf[j];
        }
        __syncthreads();
    }

    // ---- epilogue ----
    int rr[8], cc[8];
#pragma unroll
    for (int i = 0; i < 4; i++) {
        rr[i]     = m0 + ty * 4 + i;
        rr[i + 4] = m0 + 64 + ty * 4 + i;
        cc[i]     = n0 + tx * 4 + i;
        cc[i + 4] = n0 + 64 + tx * 4 + i;
    }
#pragma unroll
    for (int i = 0; i < 8; i++) {
        const int m = rr[i];
        float bb = 0.f, s = 1.f, t = 0.f;
        if (EPI == 0 || EPI == 1) bb = bias[m];
        if (EPI == 1) {
            s = gam[m] * rsqrtf(var[m] + EPSV);
            t = bet[m] - mu[m] * s;
        }
#pragma unroll
        for (int j = 0; j < 8; j++) {
            float v = acc[i][j] + bb;
            if (EPI == 1) v = fmaxf(v * s + t, 0.f);
            if (EPI == 2) v *= scale;
            C[(long long)m * N + cc[j]] = v;
        }
    }
}

// ---------------------------------------------------------------------------
// Row softmax over N=4096, one 256-thread block per row (B*N rows total).
// ---------------------------------------------------------------------------
__global__ void __launch_bounds__(256)
softmax_kernel(float* __restrict__ S)
{
    const int N = 4096;
    float* p = S + (long long)blockIdx.x * N;
    const int tid = threadIdx.x;

    float4 v[4];
    float mx = -3.4e38f;
#pragma unroll
    for (int i = 0; i < 4; i++) {
        v[i] = *(const float4*)&p[i * 1024 + tid * 4];
        mx = fmaxf(mx, fmaxf(fmaxf(v[i].x, v[i].y), fmaxf(v[i].z, v[i].w)));
    }

    __shared__ float redA[8];
    __shared__ float redB[8];
#pragma unroll
    for (int o = 16; o; o >>= 1)
        mx = fmaxf(mx, __shfl_xor_sync(0xffffffffu, mx, o));
    if ((tid & 31) == 0) redA[tid >> 5] = mx;
    __syncthreads();
#pragma unroll
    for (int w = 0; w < 8; w++) mx = fmaxf(mx, redA[w]);

    float sum = 0.f;
#pragma unroll
    for (int i = 0; i < 4; i++) {
        v[i].x = __expf(v[i].x - mx);
        v[i].y = __expf(v[i].y - mx);
        v[i].z = __expf(v[i].z - mx);
        v[i].w = __expf(v[i].w - mx);
        sum += v[i].x + v[i].y + v[i].z + v[i].w;
    }
#pragma unroll
    for (int o = 16; o; o >>= 1)
        sum += __shfl_xor_sync(0xffffffffu, sum, o);
    if ((tid & 31) == 0) redB[tid >> 5] = sum;
    __syncthreads();
    sum = 0.f;
#pragma unroll
    for (int w = 0; w < 8; w++) sum += redB[w];

    const float inv = 1.f / sum;
#pragma unroll
    for (int i = 0; i < 4; i++) {
        v[i].x *= inv; v[i].y *= inv; v[i].z *= inv; v[i].w *= inv;
        *(float4*)&p[i * 1024 + tid * 4] = v[i];
    }
}

// ---------------------------------------------------------------------------
extern "C" void kernel_launch(void* const* d_in, const int* in_sizes, int n_in,
                              void* d_out, int out_size)
{
    const float* x      = (const float*)d_in[0];
    // k branch: w1,b1,g1,beta1,m1,v1,w2,b2,g2,beta2,m2,v2 -> indices 1..12
    const float* k_w1   = (const float*)d_in[1];
    const float* k_b1   = (const float*)d_in[2];
    const float* k_g1   = (const float*)d_in[3];
    const float* k_be1  = (const float*)d_in[4];
    const float* k_m1   = (const float*)d_in[5];
    const float* k_v1   = (const float*)d_in[6];
    const float* k_w2   = (const float*)d_in[7];
    const float* k_b2   = (const float*)d_in[8];
    const float* k_g2   = (const float*)d_in[9];
    const float* k_be2  = (const float*)d_in[10];
    const float* k_m2   = (const float*)d_in[11];
    const float* k_v2   = (const float*)d_in[12];
    // q branch -> 13..24
    const float* q_w1   = (const float*)d_in[13];
    const float* q_b1   = (const float*)d_in[14];
    const float* q_g1   = (const float*)d_in[15];
    const float* q_be1  = (const float*)d_in[16];
    const float* q_m1   = (const float*)d_in[17];
    const float* q_v1   = (const float*)d_in[18];
    const float* q_w2   = (const float*)d_in[19];
    const float* q_b2   = (const float*)d_in[20];
    const float* q_g2   = (const float*)d_in[21];
    const float* q_be2  = (const float*)d_in[22];
    const float* q_m2   = (const float*)d_in[23];
    const float* q_v2   = (const float*)d_in[24];
    const float* v_w    = (const float*)d_in[25];
    const float* v_b    = (const float*)d_in[26];
    const float* o_w    = (const float*)d_in[27];
    const float* o_b    = (const float*)d_in[28];

    float *h, *Kf, *Qf, *Vf, *S, *ctx;
    cudaGetSymbolAddress((void**)&h,   g_h);
    cudaGetSymbolAddress((void**)&Kf,  g_K);
    cudaGetSymbolAddress((void**)&Qf,  g_Q);
    cudaGetSymbolAddress((void**)&Vf,  g_V);
    cudaGetSymbolAddress((void**)&S,   g_S);
    cudaGetSymbolAddress((void**)&ctx, g_ctx);

    const long long sX  = 512LL * 4096;   // per-batch x
    const long long sC  = 256LL * 4096;   // per-batch 256-ch maps
    const long long sS  = 4096LL * 4096;  // per-batch attention
    const long long sO  = 512LL * 4096;   // per-batch output

    const dim3 gProj(32, 2, 4);   // M=256, N=4096
    const dim3 gOut (32, 4, 4);   // M=512
    const dim3 gSim (32, 32, 4);  // M=N=4096

    // ---- k branch ----
    gemm_kernel<0,0,1><<<gProj, 256>>>(k_w1, 0, x, sX, h, sC,
                                       256, 4096, 512,
                                       k_b1, k_g1, k_be1, k_m1, k_v1, 0.f);
    gemm_kernel<0,0,1><<<gProj, 256>>>(k_w2, 0, h, sC, Kf, sC,
                                       256, 4096, 256,
                                       k_b2, k_g2, k_be2, k_m2, k_v2, 0.f);
    // ---- q branch ----
    gemm_kernel<0,0,1><<<gProj, 256>>>(q_w1, 0, x, sX, h, sC,
                                       256, 4096, 512,
                                       q_b1, q_g1, q_be1, q_m1, q_v1, 0.f);
    gemm_kernel<0,0,1><<<gProj, 256>>>(q_w2, 0, h, sC, Qf, sC,
                                       256, 4096, 256,
                                       q_b2, q_g2, q_be2, q_m2, q_v2, 0.f);
    // ---- value ----
    gemm_kernel<0,0,0><<<gProj, 256>>>(v_w, 0, x, sX, Vf, sC,
                                       256, 4096, 512,
                                       v_b, nullptr, nullptr, nullptr, nullptr, 0.f);
    // ---- sim = (Q^T K) * Ck^-0.5 ----  (row = query n, col = key m)
    gemm_kernel<1,0,2><<<gSim, 256>>>(Qf, sC, Kf, sC, S, sS,
                                      4096, 4096, 256,
                                      nullptr, nullptr, nullptr, nullptr, nullptr,
                                      0.0625f);
    // ---- softmax over keys (contiguous dim) ----
    softmax_kernel<<<4 * 4096, 256>>>(S);
    // ---- ctx = V P^T ----
    gemm_kernel<0,1,2><<<gProj, 256>>>(Vf, sC, S, sS, ctx, sC,
                                       256, 4096, 4096,
                                       nullptr, nullptr, nullptr, nullptr, nullptr,
                                       1.0f);
    // ---- out = Wo ctx + bo ----
    gemm_kernel<0,0,0><<<gOut, 256>>>(o_w, 0, ctx, sC, (float*)d_out, sO,
                                      512, 4096, 256,
                                      o_b, nullptr, nullptr, nullptr, nullptr, 0.f);
}

// round 3
// speedup vs baseline: 1.7087x; 1.7087x over previous
#include <cuda_runtime.h>
#include <cuda_bf16.h>
#include <cstdint>

#define EPSV 1e-5f

// ---------------------------------------------------------------------------
// Scratch
// ---------------------------------------------------------------------------
__device__ float g_h  [4LL * 256 * 4096];   // branch intermediate
__device__ float g_K  [4LL * 256 * 4096];   // Kt: [N][Ck] per batch (c contiguous)
__device__ float g_Q  [4LL * 256 * 4096];   // Qt: [N][Ck]
__device__ float g_V  [4LL * 256 * 4096];   // V:  [Cv][N] (spatial contiguous)
__device__ float g_ctx[4LL * 256 * 4096];   // ctx:[Cv][N]
__device__ float g_S  [4LL * 4096 * 4096];  // S/P: [Nq][Nk]

// ---------------------------------------------------------------------------
// tf32 helpers (sm_80+ PTX only -- must compile under plain sm_103 target)
// ---------------------------------------------------------------------------
__device__ __forceinline__ uint32_t f2tf32(float f) {
    uint32_t u;
    asm("cvt.rna.tf32.f32 %0, %1;" : "=r"(u) : "f"(f));
    return u;
}

__device__ __forceinline__ void mma_tf32(float* d, const uint32_t* a, const uint32_t* b) {
    asm volatile(
        "mma.sync.aligned.m16n8k8.row.col.f32.tf32.tf32.f32 "
        "{%0,%1,%2,%3}, {%4,%5,%6,%7}, {%8,%9}, {%0,%1,%2,%3};"
        : "+f"(d[0]), "+f"(d[1]), "+f"(d[2]), "+f"(d[3])
        : "r"(a[0]), "r"(a[1]), "r"(a[2]), "r"(a[3]),
          "r"(b[0]), "r"(b[1]));
}

// ---------------------------------------------------------------------------
// tf32 mma.sync GEMM: D[m,n] = scale * sum_k A[m,k]*B[n,k]
// A: row-major [M][K] (ldA, K contiguous), B: row-major [N][K] (ldB).
// CTA tile 128x128, BK=32, 256 threads = 8 warps (2 m x 4 n), warp tile 64x32.
// SMEM holds fragment-permuted tf32 tiles, double buffered.
//   A section per kstep: 8 mfrags * (32 lanes * 4 regs) = 1024 + 8 pad = 1032
//   B section per kstep: 16 nfrags * (32 lanes * 2 regs) = 1024 + 8 pad = 1032
//   per-operand buffer = 4*1032 = 4128 words; two buffers each.
// K % 32 == 0 required.
// ---------------------------------------------------------------------------
__global__ void __launch_bounds__(256)
gemm_mma(const float* __restrict__ A, long long sAb, int ldA,
         const float* __restrict__ B, long long sBb, int ldB,
         float* __restrict__ C, long long sCb, int ldC,
         int K, float scale)
{
    extern __shared__ uint32_t smw[];
    uint32_t* const Asm = smw;          // 2 * 4128 words
    uint32_t* const Bsm = smw + 8256;   // 2 * 4128 words

    const int tid  = threadIdx.x, lane = tid & 31, wid = tid >> 5;
    const int wm = wid >> 2, wn = wid & 3;

    const float* Ag = A + (long long)blockIdx.z * sAb + (long long)(blockIdx.y * 128) * ldA;
    const float* Bg = B + (long long)blockIdx.z * sBb + (long long)(blockIdx.x * 128) * ldB;
    float* Cg = C + (long long)blockIdx.z * sCb;
    const int m0 = blockIdx.y * 128, n0 = blockIdx.x * 128;

    // Per-thread staging offsets (chunk-invariant).
    // slot = it*256+tid -> (row 0..127, kgroup 0..7); kgroup = 4 consecutive k.
    int aSrc[4], bSrc[4], aDst[4], bDst[4];
#pragma unroll
    for (int it = 0; it < 4; ++it) {
        const int slot = it * 256 + tid;
        const int row = slot >> 3, kg = slot & 7;
        const int ks = kg >> 1, half = kg & 1;
        aSrc[it] = row * ldA + kg * 4;
        bSrc[it] = row * ldB + kg * 4;
        // A element (r,kk): lane=(r&7)*4+(kk&3), reg=(kk>=4)*2+(r>=8)
        aDst[it] = ks * 1032 + (row >> 4) * 128 + (row & 7) * 16
                 + half * 2 + ((row >> 3) & 1);
        // B element (n,kk): lane=(n&7)*4+(kk&3), reg=(kk>=4)
        bDst[it] = ks * 1032 + (row >> 3) * 64 + (row & 7) * 8 + half;
    }

    float acc[4][4][4];
#pragma unroll
    for (int i = 0; i < 4; ++i)
#pragma unroll
        for (int j = 0; j < 4; ++j)
#pragma unroll
            for (int r = 0; r < 4; ++r) acc[i][j][r] = 0.f;

    const int NCH = K >> 5;

    // ---- prologue: chunk 0 -> buffer 0 ----
#pragma unroll
    for (int it = 0; it < 4; ++it) {
        float4 va = *(const float4*)(Ag + aSrc[it]);
        float4 vb = *(const float4*)(Bg + bSrc[it]);
        uint32_t* pa = Asm + aDst[it];
        pa[0] = f2tf32(va.x); pa[4]  = f2tf32(va.y);
        pa[8] = f2tf32(va.z); pa[12] = f2tf32(va.w);
        uint32_t* pb = Bsm + bDst[it];
        pb[0] = f2tf32(vb.x); pb[2] = f2tf32(vb.y);
        pb[4] = f2tf32(vb.z); pb[6] = f2tf32(vb.w);
    }
    __syncthreads();

    const int aFragBase = wm * 512 + lane * 4;
    const int bFragBase = wn * 256 + lane * 2;

    for (int c = 0; c < NCH; ++c) {
        float4 ra[4], rb[4];
        const bool pre = (c + 1 < NCH);
        if (pre) {
            const int k0 = (c + 1) << 5;
#pragma unroll
            for (int it = 0; it < 4; ++it) {
                ra[it] = *(const float4*)(Ag + aSrc[it] + k0);
                rb[it] = *(const float4*)(Bg + bSrc[it] + k0);
            }
        }

        const uint32_t* Ab = Asm + (c & 1) * 4128;
        const uint32_t* Bb = Bsm + (c & 1) * 4128;
#pragma unroll
        for (int ks = 0; ks < 4; ++ks) {
            uint32_t af[4][4], bf[4][2];
#pragma unroll
            for (int i = 0; i < 4; ++i) {
                uint4 v = *(const uint4*)(Ab + ks * 1032 + aFragBase + i * 128);
                af[i][0] = v.x; af[i][1] = v.y; af[i][2] = v.z; af[i][3] = v.w;
            }
#pragma unroll
            for (int j = 0; j < 4; ++j) {
                uint2 v = *(const uint2*)(Bb + ks * 1032 + bFragBase + j * 64);
                bf[j][0] = v.x; bf[j][1] = v.y;
            }
#pragma unroll
            for (int i = 0; i < 4; ++i)
#pragma unroll
                for (int j = 0; j < 4; ++j)
                    mma_tf32(acc[i][j], af[i], bf[j]);
        }

        if (pre) {
            uint32_t* Aw = Asm + ((c + 1) & 1) * 4128;
            uint32_t* Bw = Bsm + ((c + 1) & 1) * 4128;
#pragma unroll
            for (int it = 0; it < 4; ++it) {
                uint32_t* pa = Aw + aDst[it];
                pa[0] = f2tf32(ra[it].x); pa[4]  = f2tf32(ra[it].y);
                pa[8] = f2tf32(ra[it].z); pa[12] = f2tf32(ra[it].w);
                uint32_t* pb = Bw + bDst[it];
                pb[0] = f2tf32(rb[it].x); pb[2] = f2tf32(rb[it].y);
                pb[4] = f2tf32(rb[it].z); pb[6] = f2tf32(rb[it].w);
            }
        }
        __syncthreads();
    }

    // ---- epilogue ----
    const int g = lane >> 2, cq = lane & 3;
#pragma unroll
    for (int i = 0; i < 4; ++i) {
        const long long r0 = m0 + wm * 64 + i * 16 + g;
#pragma unroll
        for (int j = 0; j < 4; ++j) {
            const int col = n0 + wn * 32 + j * 8 + cq * 2;
            float2 v0 = make_float2(acc[i][j][0] * scale, acc[i][j][1] * scale);
            float2 v1 = make_float2(acc[i][j][2] * scale, acc[i][j][3] * scale);
            *(float2*)&Cg[r0 * ldC + col]       = v0;
            *(float2*)&Cg[(r0 + 8) * ldC + col] = v1;
        }
    }
}

// ---------------------------------------------------------------------------
// FFMA SGEMM for the projections. C = epi(A@B), optional transposed store.
//   EPI: 0 -> + bias[m];  1 -> relu((acc+bias[m])*s[m]+t[m])
//   TRANS: 0 -> C[m*N+n];  1 -> C[n*M+m]
// ---------------------------------------------------------------------------
template <int EPI, int TRANS>
__global__ void __launch_bounds__(256)
gemm_kernel(const float* __restrict__ A,
            const float* __restrict__ B, long long sBb,
            float* __restrict__ C, long long sCb,
            int M, int N, int K,
            const float* __restrict__ bias,
            const float* __restrict__ gam, const float* __restrict__ bet,
            const float* __restrict__ mu,  const float* __restrict__ var)
{
    const int BM = 128, BN = 128, BK = 8;
    __shared__ float As[BK][BM];
    __shared__ float Bs[BK][BN];

    B += (long long)blockIdx.z * sBb;
    C += (long long)blockIdx.z * sCb;

    const int m0 = blockIdx.y * BM;
    const int n0 = blockIdx.x * BN;
    const int tid = threadIdx.x;
    const int tx = tid & 15;
    const int ty = tid >> 4;

    float acc[8][8];
#pragma unroll
    for (int i = 0; i < 8; i++)
#pragma unroll
        for (int j = 0; j < 8; j++) acc[i][j] = 0.f;

    for (int k0 = 0; k0 < K; k0 += BK) {
        {   // A[m,k], K contiguous
            const int r = tid >> 1, cg = (tid & 1) * 4;
            float4 v = *(const float4*)&A[(long long)(m0 + r) * K + k0 + cg];
            As[cg + 0][r] = v.x; As[cg + 1][r] = v.y;
            As[cg + 2][r] = v.z; As[cg + 3][r] = v.w;
        }
        {   // B[k,n], N contiguous
            const int r = tid >> 5, c4 = (tid & 31) * 4;
            float4 v = *(const float4*)&B[(long long)(k0 + r) * N + n0 + c4];
            *(float4*)&Bs[r][c4] = v;
        }
        __syncthreads();

#pragma unroll
        for (int k = 0; k < BK; k++) {
            float4 a0 = *(const float4*)&As[k][ty * 4];
            float4 a1 = *(const float4*)&As[k][64 + ty * 4];
            float4 b0 = *(const float4*)&Bs[k][tx * 4];
            float4 b1 = *(const float4*)&Bs[k][64 + tx * 4];
            float af[8] = {a0.x, a0.y, a0.z, a0.w, a1.x, a1.y, a1.z, a1.w};
            float bf[8] = {b0.x, b0.y, b0.z, b0.w, b1.x, b1.y, b1.z, b1.w};
#pragma unroll
            for (int i = 0; i < 8; i++)
#pragma unroll
                for (int j = 0; j < 8; j++)
                    acc[i][j] += af[i] * bf[j];
        }
        __syncthreads();
    }

    int rr[8], cc[8];
    float bb[8], ss[8], tt[8];
#pragma unroll
    for (int i = 0; i < 4; i++) {
        rr[i]     = m0 + ty * 4 + i;
        rr[i + 4] = m0 + 64 + ty * 4 + i;
        cc[i]     = n0 + tx * 4 + i;
        cc[i + 4] = n0 + 64 + tx * 4 + i;
    }
#pragma unroll
    for (int i = 0; i < 8; i++) {
        const int m = rr[i];
        bb[i] = bias[m];
        if (EPI == 1) {
            float s = gam[m] * rsqrtf(var[m] + EPSV);
            ss[i] = s;
            tt[i] = bet[m] - mu[m] * s;
        }
    }

    auto ev = [&](int i, int j) -> float {
        float v = acc[i][j] + bb[i];
        if (EPI == 1) v = fmaxf(v * ss[i] + tt[i], 0.f);
        return v;
    };

    if (TRANS == 0) {
#pragma unroll
        for (int i = 0; i < 8; i++) {
#pragma unroll
            for (int j = 0; j < 8; j++)
                C[(long long)rr[i] * N + cc[j]] = ev(i, j);
        }
    } else {
#pragma unroll
        for (int j = 0; j < 8; j++) {
            float4 v0 = make_float4(ev(0, j), ev(1, j), ev(2, j), ev(3, j));
            float4 v1 = make_float4(ev(4, j), ev(5, j), ev(6, j), ev(7, j));
            *(float4*)&C[(long long)cc[j] * M + m0 + ty * 4]      = v0;
            *(float4*)&C[(long long)cc[j] * M + m0 + 64 + ty * 4] = v1;
        }
    }
}

// ---------------------------------------------------------------------------
// Row softmax over N=4096, one 256-thread block per row.
// ---------------------------------------------------------------------------
__global__ void __launch_bounds__(256)
softmax_kernel(float* __restrict__ S)
{
    const int N = 4096;
    float* p = S + (long long)blockIdx.x * N;
    const int tid = threadIdx.x;

    float4 v[4];
    float mx = -3.4e38f;
#pragma unroll
    for (int i = 0; i < 4; i++) {
        v[i] = *(const float4*)&p[i * 1024 + tid * 4];
        mx = fmaxf(mx, fmaxf(fmaxf(v[i].x, v[i].y), fmaxf(v[i].z, v[i].w)));
    }

    __shared__ float redA[8];
    __shared__ float redB[8];
#pragma unroll
    for (int o = 16; o; o >>= 1)
        mx = fmaxf(mx, __shfl_xor_sync(0xffffffffu, mx, o));
    if ((tid & 31) == 0) redA[tid >> 5] = mx;
    __syncthreads();
#pragma unroll
    for (int w = 0; w < 8; w++) mx = fmaxf(mx, redA[w]);

    float sum = 0.f;
#pragma unroll
    for (int i = 0; i < 4; i++) {
        v[i].x = __expf(v[i].x - mx);
        v[i].y = __expf(v[i].y - mx);
        v[i].z = __expf(v[i].z - mx);
        v[i].w = __expf(v[i].w - mx);
        sum += v[i].x + v[i].y + v[i].z + v[i].w;
    }
#pragma unroll
    for (int o = 16; o; o >>= 1)
        sum += __shfl_xor_sync(0xffffffffu, sum, o);
    if ((tid & 31) == 0) redB[tid >> 5] = sum;
    __syncthreads();
    sum = 0.f;
#pragma unroll
    for (int w = 0; w < 8; w++) sum += redB[w];

    const float inv = 1.f / sum;
#pragma unroll
    for (int i = 0; i < 4; i++) {
        v[i].x *= inv; v[i].y *= inv; v[i].z *= inv; v[i].w *= inv;
        *(float4*)&p[i * 1024 + tid * 4] = v[i];
    }
}

// ---------------------------------------------------------------------------
extern "C" void kernel_launch(void* const* d_in, const int* in_sizes, int n_in,
                              void* d_out, int out_size)
{
    const float* x     = (const float*)d_in[0];
    const float* k_w1  = (const float*)d_in[1];
    const float* k_b1  = (const float*)d_in[2];
    const float* k_g1  = (const float*)d_in[3];
    const float* k_be1 = (const float*)d_in[4];
    const float* k_m1  = (const float*)d_in[5];
    const float* k_v1  = (const float*)d_in[6];
    const float* k_w2  = (const float*)d_in[7];
    const float* k_b2  = (const float*)d_in[8];
    const float* k_g2  = (const float*)d_in[9];
    const float* k_be2 = (const float*)d_in[10];
    const float* k_m2  = (const float*)d_in[11];
    const float* k_v2  = (const float*)d_in[12];
    const float* q_w1  = (const float*)d_in[13];
    const float* q_b1  = (const float*)d_in[14];
    const float* q_g1  = (const float*)d_in[15];
    const float* q_be1 = (const float*)d_in[16];
    const float* q_m1  = (const float*)d_in[17];
    const float* q_v1  = (const float*)d_in[18];
    const float* q_w2  = (const float*)d_in[19];
    const float* q_b2  = (const float*)d_in[20];
    const float* q_g2  = (const float*)d_in[21];
    const float* q_be2 = (const float*)d_in[22];
    const float* q_m2  = (const float*)d_in[23];
    const float* q_v2  = (const float*)d_in[24];
    const float* v_w   = (const float*)d_in[25];
    const float* v_b   = (const float*)d_in[26];
    const float* o_w   = (const float*)d_in[27];
    const float* o_b   = (const float*)d_in[28];

    float *h, *Kt, *Qt, *Vf, *S, *ctx;
    cudaGetSymbolAddress((void**)&h,   g_h);
    cudaGetSymbolAddress((void**)&Kt,  g_K);
    cudaGetSymbolAddress((void**)&Qt,  g_Q);
    cudaGetSymbolAddress((void**)&Vf,  g_V);
    cudaGetSymbolAddress((void**)&S,   g_S);
    cudaGetSymbolAddress((void**)&ctx, g_ctx);

    const long long sX = 512LL * 4096;
    const long long sC = 256LL * 4096;
    const long long sS = 4096LL * 4096;
    const long long sO = 512LL * 4096;

    const int MMA_SMEM = 16512 * 2 * 2;  // 66048 bytes
    cudaFuncSetAttribute(gemm_mma, cudaFuncAttributeMaxDynamicSharedMemorySize, MMA_SMEM);

    const dim3 gProj(32, 2, 4);   // M=256, N=4096
    const dim3 gOut (32, 4, 4);   // M=512
    const dim3 gSim (32, 32, 4);  // 4096x4096
    const dim3 gCtx (32, 2, 4);   // 256x4096

    // ---- k branch: h = relu(bn(W1 x)); Kt = relu(bn(W2 h)) stored transposed ----
    gemm_kernel<1, 0><<<gProj, 256>>>(k_w1, x, sX, h, sC, 256, 4096, 512,
                                      k_b1, k_g1, k_be1, k_m1, k_v1);
    gemm_kernel<1, 1><<<gProj, 256>>>(k_w2, h, sC, Kt, sC, 256, 4096, 256,
                                      k_b2, k_g2, k_be2, k_m2, k_v2);
    // ---- q branch ----
    gemm_kernel<1, 0><<<gProj, 256>>>(q_w1, x, sX, h, sC, 256, 4096, 512,
                                      q_b1, q_g1, q_be1, q_m1, q_v1);
    gemm_kernel<1, 1><<<gProj, 256>>>(q_w2, h, sC, Qt, sC, 256, 4096, 256,
                                      q_b2, q_g2, q_be2, q_m2, q_v2);
    // ---- value ----
    gemm_kernel<0, 0><<<gProj, 256>>>(v_w, x, sX, Vf, sC, 256, 4096, 512,
                                      v_b, nullptr, nullptr, nullptr, nullptr);

    // ---- sim[nq,nk] = 0.0625 * sum_c Qt[nq,c]*Kt[nk,c] ----
    gemm_mma<<<gSim, 256, MMA_SMEM>>>(Qt, sC, 256, Kt, sC, 256, S, sS, 4096,
                                      256, 0.0625f);
    // ---- softmax over keys ----
    softmax_kernel<<<4 * 4096, 256>>>(S);
    // ---- ctx[c,nq] = sum_m V[c,m]*P[nq,m] ----
    gemm_mma<<<gCtx, 256, MMA_SMEM>>>(Vf, sC, 4096, S, sS, 4096, ctx, sC, 4096,
                                      4096, 1.0f);
    // ---- out = Wo ctx + bo ----
    gemm_kernel<0, 0><<<gOut, 256>>>(o_w, ctx, sC, (float*)d_out, sO, 512, 4096, 256,
                                     o_b, nullptr, nullptr, nullptr, nullptr);
}

// round 4
// speedup vs baseline: 2.9320x; 1.7159x over previous
#include <cuda_runtime.h>
#include <cuda_fp16.h>
#include <cstdint>

#define EPSV 1e-5f

// ---------------------------------------------------------------------------
// Scratch (fp16 stored as unsigned short)
// ---------------------------------------------------------------------------
__device__ unsigned short g_h  [4LL * 256 * 4096];   // h:   [c][n] per batch
__device__ unsigned short g_K  [4LL * 4096 * 256];   // Kt:  [n][ck]
__device__ unsigned short g_Q  [4LL * 4096 * 256];   // Qt:  [n][ck]
__device__ unsigned short g_V  [4LL * 256 * 4096];   // V:   [c][n]
__device__ unsigned short g_ctx[4LL * 256 * 4096];   // ctx: [c][n]
__device__ float          g_S  [4LL * 4096 * 4096];  // logits fp32
__device__ unsigned short g_P  [4LL * 4096 * 4096];  // probs fp16

__device__ __forceinline__ uint32_t pack_half2(float x, float y) {
    __half2 h = __floats2half2_rn(x, y);
    return *reinterpret_cast<uint32_t*>(&h);
}

__device__ __forceinline__ void mma_f16(float* d, const uint32_t* a, const uint32_t* b) {
    asm volatile(
        "mma.sync.aligned.m16n8k16.row.col.f32.f16.f16.f32 "
        "{%0,%1,%2,%3}, {%4,%5,%6,%7}, {%8,%9}, {%0,%1,%2,%3};"
        : "+f"(d[0]), "+f"(d[1]), "+f"(d[2]), "+f"(d[3])
        : "r"(a[0]), "r"(a[1]), "r"(a[2]), "r"(a[3]),
          "r"(b[0]), "r"(b[1]));
}

// ---------------------------------------------------------------------------
// Unified fp16 mma GEMM: D[m,n] = epi( sum_k A[m,k]*B[k,n] )
//  ASRC: 0 = A fp16 [M][K] (ldA, K contig); 1 = A fp32 [M][K]
//  BSRC: 0 = B fp16 [N][K] (B[n][k], K contig)
//        1 = B fp32 [K][N] (N contig)
//        2 = B fp16 [K][N] (N contig)
//  EPI : 0 = *scale; 1 = +bias[m]; 2 = relu((acc+bias[m])*s[m]+t[m])
//  OUT : 0 = fp32 C[m*ldC+n]; 1 = fp16 C[m*ldC+n]; 2 = fp16 C[n*ldC+m]
// CTA tile 128x128, BK=32 (2 ksteps of k16), 8 warps (2m x 4n), warp 64x32.
// SMEM: fragment-permuted fp16x2 words, double buffered.
//   per kstep: A 8 mfrags * 32 lanes * 4 words = 1024 (+8 pad) = 1032 words
//              B 16 nfrags * 32 lanes * 2 words = 1024 (+8 pad) = 1032 words
//   buffer = 2*1032 = 2064 words per operand; x2 buffers.
// Requires M%128==0, N%128==0, K%32==0.
// ---------------------------------------------------------------------------
template <int ASRC, int BSRC, int EPI, int OUT>
__global__ void __launch_bounds__(256, 2)
gemm_f16(const void* __restrict__ Av, long long sAb, int ldA,
         const void* __restrict__ Bv, long long sBb, int ldB,
         void* __restrict__ Cv, long long sCb, int ldC,
         int K, float scale,
         const float* __restrict__ bias,
         const float* __restrict__ gam, const float* __restrict__ bet,
         const float* __restrict__ mu,  const float* __restrict__ var)
{
    __shared__ uint32_t smw[8256];
    uint32_t* const Asm = smw;          // 2 x 2064 words
    uint32_t* const Bsm = smw + 4128;   // 2 x 2064 words

    const int tid = threadIdx.x, lane = tid & 31, wid = tid >> 5;
    const int wm = wid >> 2, wn = wid & 3;
    const int m0 = blockIdx.y * 128, n0 = blockIdx.x * 128;
    const long long bz = blockIdx.z;

    const __half* AgH = (const __half*)Av + bz * sAb + (long long)m0 * ldA;
    const float*  AgF = (const float* )Av + bz * sAb + (long long)m0 * ldA;
    const __half* BgN = (const __half*)Bv + bz * sBb + (long long)n0 * ldB;  // BSRC0
    const float*  BgKF = (const float*)Bv + bz * sBb + n0;                   // BSRC1
    const __half* BgKH = (const __half*)Bv + bz * sBb + n0;                  // BSRC2
    float*  CgF = (float*) Cv + bz * sCb;
    __half* CgH = (__half*)Cv + bz * sCb;

    // ---- staging metadata (chunk-invariant) ----
    int aoff[4], adst[4], aaux[4];
    int boff[4], bdst[4], baux[4];
    if (ASRC == 0) {
#pragma unroll
        for (int it = 0; it < 2; ++it) {
            int slot = it * 256 + tid, row = slot >> 2, kg = slot & 3;
            aoff[it] = row * ldA + kg * 8;
            adst[it] = (kg >> 1) * 1032 + (row >> 4) * 128 + (row & 7) * 16
                     + ((row >> 3) & 1) + 2 * (kg & 1);
            aaux[it] = (row >> 1) & 3;   // store rotation
        }
    } else {
#pragma unroll
        for (int it = 0; it < 4; ++it) {
            int slot = it * 256 + tid, row = slot >> 3, kg4 = slot & 7;
            int c = kg4 & 3;
            aoff[it] = row * ldA + kg4 * 4;
            adst[it] = (kg4 >> 2) * 1032 + (row >> 4) * 128 + (row & 7) * 16
                     + ((row >> 3) & 1) + 2 * (c >> 1);
            aaux[it] = (c & 1) * 2;      // t0
        }
    }
    if (BSRC == 0) {
#pragma unroll
        for (int it = 0; it < 2; ++it) {
            int slot = it * 256 + tid, row = slot >> 2, kg = slot & 3;
            boff[it] = row * ldB + kg * 8;
            bdst[it] = (kg >> 1) * 1032 + (row >> 3) * 64 + (row & 7) * 8 + (kg & 1);
            baux[it] = (row >> 1) & 3;
        }
    } else if (BSRC == 1) {
#pragma unroll
        for (int it = 0; it < 4; ++it) {
            int slot = it * 256 + tid, k = slot >> 5, nq = (slot & 31) * 4;
            int kk = k & 15, t = (kk >> 1) & 3, reg = kk >> 3, hb = k & 1;
            boff[it] = k * ldB + nq;
            bdst[it] = 2 * ((k >> 4) * 1032 + (nq >> 3) * 64 + (nq & 7) * 8
                            + 2 * t + reg) + hb;   // half index
        }
    } else {
#pragma unroll
        for (int it = 0; it < 2; ++it) {
            int slot = it * 256 + tid, k = slot >> 4, n8 = (slot & 15) * 8;
            int kk = k & 15, t = (kk >> 1) & 3, reg = kk >> 3, hb = k & 1;
            boff[it] = k * ldB + n8;
            bdst[it] = 2 * ((k >> 4) * 1032 + (n8 >> 3) * 64 + 2 * t + reg) + hb;
        }
    }
    const int NA = (ASRC == 0) ? 2 : 4;
    const int NB = (BSRC == 1) ? 4 : 2;

    float acc[4][4][4];
#pragma unroll
    for (int i = 0; i < 4; ++i)
#pragma unroll
        for (int j = 0; j < 4; ++j)
#pragma unroll
            for (int r = 0; r < 4; ++r) acc[i][j][r] = 0.f;

    const int NCH = K >> 5;

    // ---- store helpers (as macros via lambdas) ----
    auto storeA = [&](int buf, int it, const uint4& u) {
        uint32_t* W = Asm + buf * 2064 + adst[it];
        if (ASRC == 0) {
            uint32_t ua[4] = {u.x, u.y, u.z, u.w};
#pragma unroll
            for (int s = 0; s < 4; ++s) {
                int p = (s + aaux[it]) & 3;
                W[4 * p] = ua[p];
            }
        } else {
            const float4 v = *reinterpret_cast<const float4*>(&u);
            W[4 * aaux[it]]     = pack_half2(v.x, v.y);
            W[4 * aaux[it] + 4] = pack_half2(v.z, v.w);
        }
    };
    auto storeB = [&](int buf, int it, const uint4& u) {
        if (BSRC == 0) {
            uint32_t* W = Bsm + buf * 2064 + bdst[it];
            uint32_t ua[4] = {u.x, u.y, u.z, u.w};
#pragma unroll
            for (int s = 0; s < 4; ++s) {
                int p = (s + baux[it]) & 3;
                W[2 * p] = ua[p];
            }
        } else if (BSRC == 1) {
            const float4 v = *reinterpret_cast<const float4*>(&u);
            __half* Hb = (__half*)(Bsm + buf * 2064);
            Hb[bdst[it]]      = __float2half_rn(v.x);
            Hb[bdst[it] + 16] = __float2half_rn(v.y);
            Hb[bdst[it] + 32] = __float2half_rn(v.z);
            Hb[bdst[it] + 48] = __float2half_rn(v.w);
        } else {
            __half* Hb = (__half*)(Bsm + buf * 2064);
            const __half* src = reinterpret_cast<const __half*>(&u);
#pragma unroll
            for (int q = 0; q < 8; ++q)
                Hb[bdst[it] + 16 * q] = src[q];
        }
    };
    auto loadA = [&](int it, int k0) -> uint4 {
        if (ASRC == 0) return *reinterpret_cast<const uint4*>(AgH + aoff[it] + k0);
        else           return *reinterpret_cast<const uint4*>(AgF + aoff[it] + k0);
    };
    auto loadB = [&](int it, int k0) -> uint4 {
        if (BSRC == 0)      return *reinterpret_cast<const uint4*>(BgN  + boff[it] + k0);
        else if (BSRC == 1) return *reinterpret_cast<const uint4*>(BgKF + boff[it] + (long long)k0 * ldB);
        else                return *reinterpret_cast<const uint4*>(BgKH + boff[it] + (long long)k0 * ldB);
    };

    // ---- prologue: chunk 0 -> buffer 0 ----
#pragma unroll
    for (int it = 0; it < NA; ++it) storeA(0, it, loadA(it, 0));
#pragma unroll
    for (int it = 0; it < NB; ++it) storeB(0, it, loadB(it, 0));
    __syncthreads();

    for (int c = 0; c < NCH; ++c) {
        uint4 ra[4], rb[4];
        const bool pre = (c + 1 < NCH);
        if (pre) {
            const int k0 = (c + 1) << 5;
#pragma unroll
            for (int it = 0; it < NA; ++it) ra[it] = loadA(it, k0);
#pragma unroll
            for (int it = 0; it < NB; ++it) rb[it] = loadB(it, k0);
        }

        const uint32_t* Ab = Asm + (c & 1) * 2064;
        const uint32_t* Bb = Bsm + (c & 1) * 2064;
#pragma unroll
        for (int ks = 0; ks < 2; ++ks) {
            uint4 af[4];
            uint2 bf[4];
#pragma unroll
            for (int i = 0; i < 4; ++i)
                af[i] = *reinterpret_cast<const uint4*>(Ab + ks * 1032 + (wm * 4 + i) * 128 + lane * 4);
#pragma unroll
            for (int j = 0; j < 4; ++j)
                bf[j] = *reinterpret_cast<const uint2*>(Bb + ks * 1032 + (wn * 4 + j) * 64 + lane * 2);
#pragma unroll
            for (int i = 0; i < 4; ++i)
#pragma unroll
                for (int j = 0; j < 4; ++j)
                    mma_f16(acc[i][j], reinterpret_cast<const uint32_t*>(&af[i]),
                            reinterpret_cast<const uint32_t*>(&bf[j]));
        }

        if (pre) {
            const int nb = (c + 1) & 1;
#pragma unroll
            for (int it = 0; it < NA; ++it) storeA(nb, it, ra[it]);
#pragma unroll
            for (int it = 0; it < NB; ++it) storeB(nb, it, rb[it]);
        }
        __syncthreads();
    }

    // ---- epilogue ----
    const int g = lane >> 2, cq = lane & 3;
#pragma unroll
    for (int i = 0; i < 4; ++i) {
        const int mA = m0 + wm * 64 + i * 16 + g;
        const int mB = mA + 8;
        float bA = 0.f, bB = 0.f, sA = 1.f, sB = 1.f, tA = 0.f, tB = 0.f;
        if (EPI >= 1) { bA = bias[mA]; bB = bias[mB]; }
        if (EPI == 2) {
            sA = gam[mA] * rsqrtf(var[mA] + EPSV); tA = bet[mA] - mu[mA] * sA;
            sB = gam[mB] * rsqrtf(var[mB] + EPSV); tB = bet[mB] - mu[mB] * sB;
        }
#pragma unroll
        for (int j = 0; j < 4; ++j) {
            const int col = n0 + wn * 32 + j * 8 + cq * 2;
            float v00 = acc[i][j][0], v01 = acc[i][j][1];
            float v10 = acc[i][j][2], v11 = acc[i][j][3];
            if (EPI == 0) { v00 *= scale; v01 *= scale; v10 *= scale; v11 *= scale; }
            if (EPI == 1) { v00 += bA; v01 += bA; v10 += bB; v11 += bB; }
            if (EPI == 2) {
                v00 = fmaxf(fmaf(v00 + bA, sA, tA), 0.f);
                v01 = fmaxf(fmaf(v01 + bA, sA, tA), 0.f);
                v10 = fmaxf(fmaf(v10 + bB, sB, tB), 0.f);
                v11 = fmaxf(fmaf(v11 + bB, sB, tB), 0.f);
            }
            if (OUT == 0) {
                *(float2*)&CgF[(long long)mA * ldC + col] = make_float2(v00, v01);
                *(float2*)&CgF[(long long)mB * ldC + col] = make_float2(v10, v11);
            } else if (OUT == 1) {
                *(__half2*)&CgH[(long long)mA * ldC + col] = __floats2half2_rn(v00, v01);
                *(__half2*)&CgH[(long long)mB * ldC + col] = __floats2half2_rn(v10, v11);
            } else {
                CgH[(long long)col * ldC + mA]       = __float2half_rn(v00);
                CgH[(long long)(col + 1) * ldC + mA] = __float2half_rn(v01);
                CgH[(long long)col * ldC + mB]       = __float2half_rn(v10);
                CgH[(long long)(col + 1) * ldC + mB] = __float2half_rn(v11);
            }
        }
    }
}

// ---------------------------------------------------------------------------
// Row softmax: S fp32 [row][4096] -> P fp16, one 256-thread block per row.
// ---------------------------------------------------------------------------
__global__ void __launch_bounds__(256)
softmax_kernel(const float* __restrict__ S, __half* __restrict__ P)
{
    const int N = 4096;
    const float* p = S + (long long)blockIdx.x * N;
    __half* po = P + (long long)blockIdx.x * N;
    const int tid = threadIdx.x;

    float4 v[4];
    float mx = -3.4e38f;
#pragma unroll
    for (int i = 0; i < 4; i++) {
        v[i] = *(const float4*)&p[i * 1024 + tid * 4];
        mx = fmaxf(mx, fmaxf(fmaxf(v[i].x, v[i].y), fmaxf(v[i].z, v[i].w)));
    }

    __shared__ float redA[8];
    __shared__ float redB[8];
#pragma unroll
    for (int o = 16; o; o >>= 1)
        mx = fmaxf(mx, __shfl_xor_sync(0xffffffffu, mx, o));
    if ((tid & 31) == 0) redA[tid >> 5] = mx;
    __syncthreads();
#pragma unroll
    for (int w = 0; w < 8; w++) mx = fmaxf(mx, redA[w]);

    float sum = 0.f;
#pragma unroll
    for (int i = 0; i < 4; i++) {
        v[i].x = __expf(v[i].x - mx);
        v[i].y = __expf(v[i].y - mx);
        v[i].z = __expf(v[i].z - mx);
        v[i].w = __expf(v[i].w - mx);
        sum += v[i].x + v[i].y + v[i].z + v[i].w;
    }
#pragma unroll
    for (int o = 16; o; o >>= 1)
        sum += __shfl_xor_sync(0xffffffffu, sum, o);
    if ((tid & 31) == 0) redB[tid >> 5] = sum;
    __syncthreads();
    sum = 0.f;
#pragma unroll
    for (int w = 0; w < 8; w++) sum += redB[w];

    const float inv = 1.f / sum;
#pragma unroll
    for (int i = 0; i < 4; i++) {
        __half2* q = (__half2*)&po[i * 1024 + tid * 4];
        q[0] = __floats2half2_rn(v[i].x * inv, v[i].y * inv);
        q[1] = __floats2half2_rn(v[i].z * inv, v[i].w * inv);
    }
}

// ---------------------------------------------------------------------------
extern "C" void kernel_launch(void* const* d_in, const int* in_sizes, int n_in,
                              void* d_out, int out_size)
{
    const float* x     = (const float*)d_in[0];
    const float* k_w1  = (const float*)d_in[1];
    const float* k_b1  = (const float*)d_in[2];
    const float* k_g1  = (const float*)d_in[3];
    const float* k_be1 = (const float*)d_in[4];
    const float* k_m1  = (const float*)d_in[5];
    const float* k_v1  = (const float*)d_in[6];
    const float* k_w2  = (const float*)d_in[7];
    const float* k_b2  = (const float*)d_in[8];
    const float* k_g2  = (const float*)d_in[9];
    const float* k_be2 = (const float*)d_in[10];
    const float* k_m2  = (const float*)d_in[11];
    const float* k_v2  = (const float*)d_in[12];
    const float* q_w1  = (const float*)d_in[13];
    const float* q_b1  = (const float*)d_in[14];
    const float* q_g1  = (const float*)d_in[15];
    const float* q_be1 = (const float*)d_in[16];
    const float* q_m1  = (const float*)d_in[17];
    const float* q_v1  = (const float*)d_in[18];
    const float* q_w2  = (const float*)d_in[19];
    const float* q_b2  = (const float*)d_in[20];
    const float* q_g2  = (const float*)d_in[21];
    const float* q_be2 = (const float*)d_in[22];
    const float* q_m2  = (const float*)d_in[23];
    const float* q_v2  = (const float*)d_in[24];
    const float* v_w   = (const float*)d_in[25];
    const float* v_b   = (const float*)d_in[26];
    const float* o_w   = (const float*)d_in[27];
    const float* o_b   = (const float*)d_in[28];

    void *h, *Kt, *Qt, *Vf, *S, *P, *ctx;
    cudaGetSymbolAddress(&h,   g_h);
    cudaGetSymbolAddress(&Kt,  g_K);
    cudaGetSymbolAddress(&Qt,  g_Q);
    cudaGetSymbolAddress(&Vf,  g_V);
    cudaGetSymbolAddress(&S,   g_S);
    cudaGetSymbolAddress(&P,   g_P);
    cudaGetSymbolAddress(&ctx, g_ctx);

    const long long sX = 512LL * 4096;   // x per batch (fp32)
    const long long sC = 256LL * 4096;   // 256-ch fp16 maps / Kt,Qt
    const long long sS = 4096LL * 4096;  // attention per batch
    const long long sO = 512LL * 4096;   // output per batch

    const dim3 gProj(32, 2, 4);
    const dim3 gOut (32, 4, 4);
    const dim3 gSim (32, 32, 4);

    // ---- k branch ----
    gemm_f16<1, 1, 2, 1><<<gProj, 256>>>(k_w1, 0, 512, x, sX, 4096, h, sC, 4096,
                                         512, 0.f, k_b1, k_g1, k_be1, k_m1, k_v1);
    gemm_f16<1, 2, 2, 2><<<gProj, 256>>>(k_w2, 0, 256, h, sC, 4096, Kt, sC, 256,
                                         256, 0.f, k_b2, k_g2, k_be2, k_m2, k_v2);
    // ---- q branch ----
    gemm_f16<1, 1, 2, 1><<<gProj, 256>>>(q_w1, 0, 512, x, sX, 4096, h, sC, 4096,
                                         512, 0.f, q_b1, q_g1, q_be1, q_m1, q_v1);
    gemm_f16<1, 2, 2, 2><<<gProj, 256>>>(q_w2, 0, 256, h, sC, 4096, Qt, sC, 256,
                                         256, 0.f, q_b2, q_g2, q_be2, q_m2, q_v2);
    // ---- value ----
    gemm_f16<1, 1, 1, 1><<<gProj, 256>>>(v_w, 0, 512, x, sX, 4096, Vf, sC, 4096,
                                         512, 0.f, v_b, nullptr, nullptr, nullptr, nullptr);
    // ---- sim[nq,nk] = 0.0625 * <Qt[nq,:], Kt[nk,:]> ----
    gemm_f16<0, 0, 0, 0><<<gSim, 256>>>(Qt, sC, 256, Kt, sC, 256, S, sS, 4096,
                                        256, 0.0625f, nullptr, nullptr, nullptr, nullptr, nullptr);
    // ---- softmax over keys, fp16 out ----
    softmax_kernel<<<4 * 4096, 256>>>((const float*)S, (__half*)P);
    // ---- ctx[c,nq] = sum_m V[c,m] * P[nq,m] ----
    gemm_f16<0, 0, 0, 1><<<gProj, 256>>>(Vf, sC, 4096, P, sS, 4096, ctx, sC, 4096,
                                         4096, 1.0f, nullptr, nullptr, nullptr, nullptr, nullptr);
    // ---- out = Wo ctx + bo ----
    gemm_f16<1, 2, 1, 0><<<gOut, 256>>>(o_w, 0, 256, ctx, sC, 4096, d_out, sO, 4096,
                                        256, 0.f, o_b, nullptr, nullptr, nullptr, nullptr);
}